// round 1
// baseline (speedup 1.0000x reference)
#include <cuda_runtime.h>
#include <math.h>

#define BB 16
#define NN 1024
#define CC 64
#define CIN 16

// ---------------- static device scratch ----------------
__device__ float g_att [BB*NN*NN];   // 64 MB
__device__ float g_gl  [BB*NN*NN];   // 64 MB
__device__ float g_g1  [NN*NN];
__device__ float g_g2  [NN*NN];
__device__ float g_d   [2*NN];
__device__ float g_h0a [BB*CC*NN];
__device__ float g_h0  [BB*CC*NN];
__device__ float g_hT  [BB*CC*NN];
__device__ float g_xatt[BB*CC*NN];
__device__ float g_xuai[BB*CC*NN];
__device__ float g_l1x [BB*CC*NN];
__device__ float g_l2x [BB*CC*NN];
__device__ float g_t1  [BB*CC*NN];
__device__ float g_u1  [BB*CC*NN];
__device__ float g_acc1[BB*CC*NN];
__device__ float g_sum1[BB*CC*NN];
__device__ float g_t2  [BB*CC*NN];
__device__ float g_u2  [BB*CC*NN];
__device__ float g_acc2[BB*CC*NN];
__device__ float g_sum2[BB*CC*NN];
__device__ float g_s1  [BB*NN];
__device__ float g_s2  [BB*NN];
__device__ float g_sq  [BB*NN];
__device__ float g_stats[2*BB*2];   // [path][b] -> {mean, rstd}

// ---------------- laplacian prep ----------------
// d[k][i] = rsqrt(sum_j (graph[k,i,j]) + 1)   (the +1 is the eye diagonal)
__global__ void k_lap_d(const float* __restrict__ graph) {
    int i = blockIdx.x, k = blockIdx.y, t = threadIdx.x;
    const float* row = graph + (size_t)k*NN*NN + (size_t)i*NN;
    float s = 0.f;
    for (int j = t; j < NN; j += 256) s += row[j];
    __shared__ float sh[256];
    sh[t] = s; __syncthreads();
    for (int o = 128; o > 0; o >>= 1) { if (t < o) sh[t] += sh[t+o]; __syncthreads(); }
    if (t == 0) g_d[k*NN + i] = rsqrtf(sh[0] + 1.0f);
}

// g_k[a,b] = (graph[k][b,a] + (a==b)) * d[a] * d[b]
__global__ void k_lap_scale(const float* __restrict__ graph) {
    __shared__ float tile[32][33];
    int k = blockIdx.z;
    int bx = blockIdx.x * 32, by = blockIdx.y * 32;
    const float* gsrc = graph + (size_t)k*NN*NN;
    for (int r = threadIdx.y; r < 32; r += 8) {
        int row = by + r, col = bx + threadIdx.x;
        float v = gsrc[(size_t)row*NN + col];
        if (row == col) v += 1.f;
        tile[r][threadIdx.x] = v;
    }
    __syncthreads();
    float* gout = (k == 0) ? g_g1 : g_g2;
    const float* d = g_d + k*NN;
    for (int r = threadIdx.y; r < 32; r += 8) {
        int a = bx + r, b_ = by + threadIdx.x;
        gout[(size_t)a*NN + b_] = tile[threadIdx.x][r] * d[a] * d[b_];
    }
}

// ---------------- embedding stage 1 ----------------
// h0a[b,e,n] = leakyrelu( sum_c emb_w[e,c]*x[b,c,n] + emb_b[e] )
__global__ void k_emb1(const float* __restrict__ x, const float* __restrict__ emb_w,
                       const float* __restrict__ emb_b) {
    __shared__ float w[CC*CIN];
    __shared__ float bsm[CC];
    int t = threadIdx.x;
    for (int i = t; i < CC*CIN; i += 256) w[i] = emb_w[i];
    if (t < CC) bsm[t] = emb_b[t];
    __syncthreads();
    int b = blockIdx.x;
    int n = blockIdx.y * 256 + t;
    float xv[CIN];
    const float* xp = x + (size_t)b*CIN*NN + n;
#pragma unroll
    for (int c = 0; c < CIN; c++) xv[c] = xp[(size_t)c*NN];
    float* out = g_h0a + (size_t)b*CC*NN + n;
    for (int e = 0; e < CC; e++) {
        float s = bsm[e];
#pragma unroll
        for (int c = 0; c < CIN; c++) s = fmaf(w[e*CIN + c], xv[c], s);
        out[(size_t)e*NN] = (s > 0.f) ? s : 0.01f*s;
    }
}

// ---------------- main [64,N] x [N,N] GEMM ----------------
// C[b,c,m] = sum_n A[b,c,n] * G[n,m]  (TRANS=0)   or   G[m,n] (TRANS=1)
// G offset = blockIdx.y * gStride (0 => shared across batch)
// epilogue: + bias[m], + addend[b,c,m], optional relu
template<int TRANS>
__global__ void gemm64(const float* __restrict__ A, const float* __restrict__ G,
                       size_t gStride, const float* __restrict__ bias,
                       const float* __restrict__ addend, int doRelu,
                       float* __restrict__ C) {
    const int b  = blockIdx.y;
    const int m0 = blockIdx.x * 64;
    const float* Ab = A + (size_t)b*CC*NN;
    const float* Gb = G + (size_t)b*gStride;
    __shared__ float As[16][65];
    __shared__ float Gs[16][65];
    int tid = threadIdx.x;
    int tx = tid & 15;
    int ty = tid >> 4;
    float acc[4][4] = {};
    for (int k0 = 0; k0 < NN; k0 += 16) {
        { // load A tile: As[kk][c]
            int c   = tid >> 2;
            int kk4 = (tid & 3) * 4;
            float4 v = *reinterpret_cast<const float4*>(Ab + (size_t)c*NN + k0 + kk4);
            As[kk4+0][c] = v.x; As[kk4+1][c] = v.y; As[kk4+2][c] = v.z; As[kk4+3][c] = v.w;
        }
        if (TRANS == 0) {
            int kk = tid >> 6;
            int m  = tid & 63;
#pragma unroll
            for (int q = 0; q < 4; q++)
                Gs[kk + 4*q][m] = Gb[(size_t)(k0 + kk + 4*q)*NN + m0 + m];
        } else {
            int m   = tid >> 2;
            int kk4 = (tid & 3) * 4;
            float4 v = *reinterpret_cast<const float4*>(Gb + (size_t)(m0+m)*NN + k0 + kk4);
            Gs[kk4+0][m] = v.x; Gs[kk4+1][m] = v.y; Gs[kk4+2][m] = v.z; Gs[kk4+3][m] = v.w;
        }
        __syncthreads();
#pragma unroll
        for (int kk = 0; kk < 16; kk++) {
            float a[4], g[4];
#pragma unroll
            for (int i = 0; i < 4; i++) a[i] = As[kk][ty + 16*i];
#pragma unroll
            for (int j = 0; j < 4; j++) g[j] = Gs[kk][tx + 16*j];
#pragma unroll
            for (int i = 0; i < 4; i++)
#pragma unroll
                for (int j = 0; j < 4; j++) acc[i][j] = fmaf(a[i], g[j], acc[i][j]);
        }
        __syncthreads();
    }
    float* Cb = C + (size_t)b*CC*NN;
    const float* Addb = addend ? addend + (size_t)b*CC*NN : nullptr;
#pragma unroll
    for (int i = 0; i < 4; i++) {
        int c = ty + 16*i;
#pragma unroll
        for (int j = 0; j < 4; j++) {
            int m = m0 + tx + 16*j;
            float v = acc[i][j];
            if (bias) v += bias[m];
            if (Addb) v += Addb[(size_t)c*NN + m];
            if (doRelu) v = fmaxf(v, 0.f);
            Cb[(size_t)c*NN + m] = v;
        }
    }
}

// ---------------- 64x64 channel mix ----------------
// out[b,o,n] = sum_k M_eff[o,k]*in[b,k,n] + bias[o]
// MTRANS=0: M_eff[o,k]=M[o*64+k];  MTRANS=1: M_eff[o,k]=M[k*64+o]
template<int MTRANS>
__global__ void chanmix(const float* __restrict__ in, const float* __restrict__ M,
                        const float* __restrict__ bias, float* __restrict__ out) {
    __shared__ float Ms[64][65];
    __shared__ float Xs[64][65];
    int tid = threadIdx.x;
    int b = blockIdx.y, n0 = blockIdx.x * 64;
    for (int i = tid; i < 64*64; i += 256) {
        int r = i >> 6, c = i & 63;
        Ms[r][c] = MTRANS ? M[c*64 + r] : M[i];
    }
    const float* inb = in + (size_t)b*CC*NN + n0;
    for (int i = tid; i < 64*64; i += 256) {
        int k = i >> 6, n = i & 63;
        Xs[k][n] = inb[(size_t)k*NN + n];
    }
    __syncthreads();
    int tx = tid & 15, ty = tid >> 4;
    float acc[4][4] = {};
#pragma unroll 8
    for (int k = 0; k < 64; k++) {
        float m[4], xv[4];
#pragma unroll
        for (int i = 0; i < 4; i++) m[i] = Ms[ty + 16*i][k];
#pragma unroll
        for (int j = 0; j < 4; j++) xv[j] = Xs[k][tx + 16*j];
#pragma unroll
        for (int i = 0; i < 4; i++)
#pragma unroll
            for (int j = 0; j < 4; j++) acc[i][j] = fmaf(m[i], xv[j], acc[i][j]);
    }
    float* outb = out + (size_t)b*CC*NN + n0;
#pragma unroll
    for (int i = 0; i < 4; i++) {
        int o = ty + 16*i;
        float bv = bias ? bias[o] : 0.f;
#pragma unroll
        for (int j = 0; j < 4; j++)
            outb[(size_t)o*NN + tx + 16*j] = acc[i][j] + bv;
    }
}

// ---------------- attention scores (rank-1) ----------------
__global__ void k_s12(const float* __restrict__ att_a) {
    __shared__ float a1[64], a2[64];
    int t = threadIdx.x;
    if (t < 64) a1[t] = att_a[t];
    else if (t < 128) a2[t-64] = att_a[t];
    __syncthreads();
    int b = blockIdx.x;
    int i = blockIdx.y * 256 + t;
    const float* h = g_hT + (size_t)b*CC*NN + i;
    float v1 = 0.f, v2 = 0.f;
#pragma unroll 8
    for (int c = 0; c < 64; c++) {
        float hv = h[(size_t)c*NN];
        v1 = fmaf(hv, a1[c], v1);
        v2 = fmaf(hv, a2[c], v2);
    }
    g_s1[b*NN + i] = v1;
    g_s2[b*NN + i] = v2;
}

// att[b,i,:] = softmax_j leakyrelu(s1[b,i] + s2[b,j])
__global__ void k_attrow() {
    int b = blockIdx.y, i = blockIdx.x, t = threadIdx.x;
    float s1 = g_s1[b*NN + i];
    const float* s2 = g_s2 + b*NN;
    float v[4];
    float mx = -1e30f;
#pragma unroll
    for (int q = 0; q < 4; q++) {
        float e = s1 + s2[t + 256*q];
        e = (e > 0.f) ? e : 0.01f*e;
        v[q] = e;
        mx = fmaxf(mx, e);
    }
    __shared__ float sh[256];
    sh[t] = mx; __syncthreads();
    for (int o = 128; o > 0; o >>= 1) { if (t < o) sh[t] = fmaxf(sh[t], sh[t+o]); __syncthreads(); }
    mx = sh[0]; __syncthreads();
    float sm = 0.f;
#pragma unroll
    for (int q = 0; q < 4; q++) { v[q] = expf(v[q] - mx); sm += v[q]; }
    sh[t] = sm; __syncthreads();
    for (int o = 128; o > 0; o >>= 1) { if (t < o) sh[t] += sh[t+o]; __syncthreads(); }
    float inv = 1.f / sh[0];
    float* arow = g_att + ((size_t)b*NN + i)*NN;
#pragma unroll
    for (int q = 0; q < 4; q++) arow[t + 256*q] = v[q] * inv;
}

// ---------------- learned adjacency (gram + rbf) ----------------
__global__ void k_sq() {
    int b = blockIdx.x, n = blockIdx.y * 256 + threadIdx.x;
    const float* xp = g_xuai + (size_t)b*CC*NN + n;
    float s = 0.f;
#pragma unroll 8
    for (int c = 0; c < CC; c++) { float v = xp[(size_t)c*NN]; s = fmaf(v, v, s); }
    g_sq[b*NN + n] = s;
}

// gl_pre[b,i,j] = exp( exp(-max(sq_i+sq_j-2*P_ij,0)/128) + (i==j) )
__global__ void k_gram() {
    int b = blockIdx.z;
    int i0 = blockIdx.x * 64, j0 = blockIdx.y * 64;
    __shared__ float Xi[64][65], Xj[64][65];
    const float* X = g_xuai + (size_t)b*CC*NN;
    int tid = threadIdx.x;
    for (int p = tid; p < 64*64; p += 256) {
        int c = p >> 6, q = p & 63;
        Xi[c][q] = X[(size_t)c*NN + i0 + q];
        Xj[c][q] = X[(size_t)c*NN + j0 + q];
    }
    __syncthreads();
    int tx = tid & 15, ty = tid >> 4;
    float acc[4][4] = {};
#pragma unroll 8
    for (int c = 0; c < 64; c++) {
        float a[4], g[4];
#pragma unroll
        for (int p = 0; p < 4; p++) a[p] = Xi[c][ty + 16*p];
#pragma unroll
        for (int q = 0; q < 4; q++) g[q] = Xj[c][tx + 16*q];
#pragma unroll
        for (int p = 0; p < 4; p++)
#pragma unroll
            for (int q = 0; q < 4; q++) acc[p][q] = fmaf(a[p], g[q], acc[p][q]);
    }
    const float* sq = g_sq + b*NN;
    float* glb = g_gl + (size_t)b*NN*NN;
#pragma unroll
    for (int p = 0; p < 4; p++) {
        int i = i0 + ty + 16*p;
        float sqi = sq[i];
#pragma unroll
        for (int q = 0; q < 4; q++) {
            int j = j0 + tx + 16*q;
            float d2 = fmaxf(sqi + sq[j] - 2.f*acc[p][q], 0.f);
            float m = expf(-d2 * (1.f/128.f)) + ((i == j) ? 1.f : 0.f);
            glb[(size_t)i*NN + j] = expf(m);
        }
    }
}

__global__ void k_rownorm() {
    int b = blockIdx.y, i = blockIdx.x, t = threadIdx.x;
    float* row = g_gl + ((size_t)b*NN + i)*NN;
    float v[4]; float s = 0.f;
#pragma unroll
    for (int q = 0; q < 4; q++) { v[q] = row[t + 256*q]; s += v[q]; }
    __shared__ float sh[256];
    sh[t] = s; __syncthreads();
    for (int o = 128; o > 0; o >>= 1) { if (t < o) sh[t] += sh[t+o]; __syncthreads(); }
    float inv = 1.f / sh[0];
#pragma unroll
    for (int q = 0; q < 4; q++) row[t + 256*q] = v[q] * inv;
}

// ---------------- layernorm stats + final fuse ----------------
__global__ void k_lnstats(const float* __restrict__ z1, const float* __restrict__ z2) {
    int b = blockIdx.x, path = blockIdx.y, t = threadIdx.x;
    const float* z = (path ? z2 : z1) + (size_t)b*CC*NN;
    float s = 0.f, ss = 0.f;
    for (int i = t; i < CC*NN; i += 1024) { float v = z[i]; s += v; ss = fmaf(v, v, ss); }
    __shared__ float shs[1024], shq[1024];
    shs[t] = s; shq[t] = ss; __syncthreads();
    for (int o = 512; o > 0; o >>= 1) {
        if (t < o) { shs[t] += shs[t+o]; shq[t] += shq[t+o]; }
        __syncthreads();
    }
    if (t == 0) {
        float mean = shs[0] * (1.f/65536.f);
        float var  = shq[0] * (1.f/65536.f) - mean*mean;
        g_stats[(path*BB + b)*2 + 0] = mean;
        g_stats[(path*BB + b)*2 + 1] = rsqrtf(var + 1e-5f);
    }
}

__global__ void k_final(const float* __restrict__ ct, const float* __restrict__ ln_w,
                        const float* __restrict__ ln_b, float* __restrict__ out) {
    size_t idx = (size_t)blockIdx.x * 256 + threadIdx.x;
    int b  = (int)(idx / (CC*NN));
    int cn = (int)(idx % (CC*NN));
    float m1 = g_stats[b*2 + 0],            r1 = g_stats[b*2 + 1];
    float m2 = g_stats[(BB + b)*2 + 0],     r2 = g_stats[(BB + b)*2 + 1];
    float w = ln_w[cn], bb = ln_b[cn];
    float xnew = (g_sum1[idx] - m1) * r1 * w + bb;
    float z2   = (g_sum2[idx] - m2) * r2 * w + bb;
    float ft = 0.5f * z2 * (1.f + erff(z2 * 0.70710678118654752f));
    float ctv = ct[idx];
    float ctn = xnew + ft * (ctv - xnew);
    float el  = (ctn > 0.f) ? ctn : expm1f(ctn);
    float xu  = g_xuai[idx];
    float ht  = xu + ft * (el - xu);
    out[idx] = ht;
    out[(size_t)BB*CC*NN + idx] = ctn;
}

// ---------------- host launch ----------------
struct DevPtrs {
    float *att, *gl, *g1, *g2, *h0a, *h0, *hT, *xatt, *xuai;
    float *l1x, *l2x, *t1, *u1, *acc1, *sum1, *t2, *u2, *acc2, *sum2;
    bool init;
};
static DevPtrs P = {};

static void init_ptrs() {
    if (P.init) return;
    void* p;
#define GET(sym, field) cudaGetSymbolAddress(&p, sym); P.field = (float*)p;
    GET(g_att, att)  GET(g_gl, gl)   GET(g_g1, g1)   GET(g_g2, g2)
    GET(g_h0a, h0a)  GET(g_h0, h0)   GET(g_hT, hT)   GET(g_xatt, xatt)
    GET(g_xuai, xuai) GET(g_l1x, l1x) GET(g_l2x, l2x)
    GET(g_t1, t1)    GET(g_u1, u1)   GET(g_acc1, acc1) GET(g_sum1, sum1)
    GET(g_t2, t2)    GET(g_u2, u2)   GET(g_acc2, acc2) GET(g_sum2, sum2)
#undef GET
    P.init = true;
}

extern "C" void kernel_launch(void* const* d_in, const int* in_sizes, int n_in,
                              void* d_out, int out_size) {
    const float* x      = (const float*)d_in[0];
    const float* ct     = (const float*)d_in[1];
    const float* graph  = (const float*)d_in[2];
    const float* emb_w  = (const float*)d_in[3];
    const float* emb_b  = (const float*)d_in[4];
    const float* emb2_w = (const float*)d_in[5];
    const float* emb2_b = (const float*)d_in[6];
    const float* att_W  = (const float*)d_in[7];
    const float* att_a  = (const float*)d_in[8];
    // d_in[9] = att_GL : unused (adj_att > 0 everywhere => mask is a no-op)
    const float* uai_w  = (const float*)d_in[10];
    const float* uai_b  = (const float*)d_in[11];
    const float* lin1_w = (const float*)d_in[12];
    const float* lin2_w = (const float*)d_in[13];
    const float* lin2_b = (const float*)d_in[14];
    const float* ln_w   = (const float*)d_in[15];
    const float* ln_b   = (const float*)d_in[16];
    float* out = (float*)d_out;

    init_ptrs();

    const dim3 gemmGrid(NN/64, BB);
    const size_t GSTRIDE = (size_t)NN * NN;

    // graph laplacians
    k_lap_d    <<<dim3(NN, 2), 256>>>(graph);
    k_lap_scale<<<dim3(32, 32, 2), dim3(32, 8)>>>(graph);

    // embedding
    k_emb1<<<dim3(BB, NN/256), 256>>>(x, emb_w, emb_b);
    gemm64<1><<<gemmGrid, 256>>>(P.h0a, emb2_w, 0, emb2_b, nullptr, 0, P.h0);

    // attention
    chanmix<1><<<gemmGrid, 256>>>(P.h0, att_W, nullptr, P.hT);
    k_s12   <<<dim3(BB, NN/256), 256>>>(att_a);
    k_attrow<<<dim3(NN, BB), 256>>>();
    gemm64<1><<<gemmGrid, 256>>>(P.hT, P.att, GSTRIDE, nullptr, nullptr, 1, P.xatt);

    // UAI linear
    chanmix<0><<<gemmGrid, 256>>>(P.xatt, uai_w, uai_b, P.xuai);

    // learned adjacency gl
    k_sq     <<<dim3(BB, NN/256), 256>>>();
    k_gram   <<<dim3(16, 16, BB), 256>>>();
    k_rownorm<<<dim3(NN, BB), 256>>>();

    // l1 / l2 propagation
    chanmix<0><<<gemmGrid, 256>>>(P.xuai, lin1_w, nullptr, P.l1x);
    chanmix<0><<<gemmGrid, 256>>>(P.xuai, lin2_w, lin2_b, P.l2x);

    gemm64<0><<<gemmGrid, 256>>>(P.l1x, P.gl, GSTRIDE, nullptr, nullptr, 0, P.acc1);
    gemm64<0><<<gemmGrid, 256>>>(P.l1x, P.g1, 0, nullptr, nullptr, 0, P.t1);
    chanmix<0><<<gemmGrid, 256>>>(P.t1, lin1_w, nullptr, P.u1);
    gemm64<0><<<gemmGrid, 256>>>(P.u1, P.g2, 0, nullptr, P.acc1, 0, P.sum1);

    gemm64<0><<<gemmGrid, 256>>>(P.l2x, P.gl, GSTRIDE, nullptr, nullptr, 0, P.acc2);
    gemm64<0><<<gemmGrid, 256>>>(P.l2x, P.g1, 0, nullptr, nullptr, 0, P.t2);
    chanmix<0><<<gemmGrid, 256>>>(P.t2, lin2_w, lin2_b, P.u2);
    gemm64<0><<<gemmGrid, 256>>>(P.u2, P.g2, 0, nullptr, P.acc2, 0, P.sum2);

    // layernorm + gates + output
    k_lnstats<<<dim3(BB, 2), 1024>>>(P.sum1, P.sum2);
    k_final  <<<(BB*CC*NN)/256, 256>>>(ct, ln_w, ln_b, out);
}

// round 2
// speedup vs baseline: 1.4570x; 1.4570x over previous
#include <cuda_runtime.h>
#include <math.h>

#define BB 16
#define NN 1024
#define CC 64
#define CIN 16

typedef unsigned long long u64;

__device__ __forceinline__ u64 splat2(float v) {
    u64 r; asm("mov.b64 %0, {%1, %1};" : "=l"(r) : "f"(v)); return r;
}
__device__ __forceinline__ void ffma2(u64& d, u64 a, u64 b) {
    asm("fma.rn.f32x2 %0, %1, %2, %0;" : "+l"(d) : "l"(a), "l"(b));
}
__device__ __forceinline__ float2 unpack2(u64 v) {
    float2 r; asm("mov.b64 {%0, %1}, %2;" : "=f"(r.x), "=f"(r.y) : "l"(v)); return r;
}

// ---------------- static device scratch ----------------
__device__ float g_att [BB*NN*NN];
__device__ float g_gl  [BB*NN*NN];
__device__ float g_g1  [NN*NN];
__device__ float g_g2  [NN*NN];
__device__ float g_d   [2*NN];
__device__ float g_h0a [BB*CC*NN];
__device__ float g_h0  [BB*CC*NN];
__device__ float g_hT  [BB*CC*NN];
__device__ float g_xatt[BB*CC*NN];
__device__ float g_xuai[BB*CC*NN];
__device__ float g_l12 [BB*2*CC*NN];   // stacked lin1|lin2
__device__ float g_t12 [BB*2*CC*NN];
__device__ float g_u12 [BB*2*CC*NN];
__device__ float g_a12 [BB*2*CC*NN];
__device__ float g_s12x[BB*2*CC*NN];
__device__ float g_s1  [BB*NN];
__device__ float g_s2  [BB*NN];
__device__ float g_sq  [BB*NN];
__device__ float g_stats[2*BB*2];

// ---------------- laplacian prep ----------------
__global__ void k_lap_d(const float* __restrict__ graph) {
    int i = blockIdx.x, k = blockIdx.y, t = threadIdx.x;
    const float* row = graph + (size_t)k*NN*NN + (size_t)i*NN;
    float s = 0.f;
    for (int j = t; j < NN; j += 256) s += row[j];
    __shared__ float sh[256];
    sh[t] = s; __syncthreads();
    for (int o = 128; o > 0; o >>= 1) { if (t < o) sh[t] += sh[t+o]; __syncthreads(); }
    if (t == 0) g_d[k*NN + i] = rsqrtf(sh[0] + 1.0f);
}

__global__ void k_lap_scale(const float* __restrict__ graph) {
    __shared__ float tile[32][33];
    int k = blockIdx.z;
    int bx = blockIdx.x * 32, by = blockIdx.y * 32;
    const float* gsrc = graph + (size_t)k*NN*NN;
    for (int r = threadIdx.y; r < 32; r += 8) {
        int row = by + r, col = bx + threadIdx.x;
        float v = gsrc[(size_t)row*NN + col];
        if (row == col) v += 1.f;
        tile[r][threadIdx.x] = v;
    }
    __syncthreads();
    float* gout = (k == 0) ? g_g1 : g_g2;
    const float* d = g_d + k*NN;
    for (int r = threadIdx.y; r < 32; r += 8) {
        int a = bx + r, b_ = by + threadIdx.x;
        gout[(size_t)a*NN + b_] = tile[threadIdx.x][r] * d[a] * d[b_];
    }
}

// ---------------- embedding stage 1 ----------------
__global__ void k_emb1(const float* __restrict__ x, const float* __restrict__ emb_w,
                       const float* __restrict__ emb_b) {
    __shared__ float w[CC*CIN];
    __shared__ float bsm[CC];
    int t = threadIdx.x;
    for (int i = t; i < CC*CIN; i += 256) w[i] = emb_w[i];
    if (t < CC) bsm[t] = emb_b[t];
    __syncthreads();
    int b = blockIdx.x;
    int n = blockIdx.y * 256 + t;
    float xv[CIN];
    const float* xp = x + (size_t)b*CIN*NN + n;
#pragma unroll
    for (int c = 0; c < CIN; c++) xv[c] = xp[(size_t)c*NN];
    float* out = g_h0a + (size_t)b*CC*NN + n;
    for (int e = 0; e < CC; e++) {
        float s = bsm[e];
#pragma unroll
        for (int c = 0; c < CIN; c++) s = fmaf(w[e*CIN + c], xv[c], s);
        out[(size_t)e*NN] = (s > 0.f) ? s : 0.01f*s;
    }
}

// ================= gemm128: C[b, 0..127, m] = sum_k A[b,c,k] * G[k,m] =================
// A batch stride 128*NN, G batch stride gStride (0 = shared). Optional addend.
#define PADA 132
#define PADG 68
__global__ void __launch_bounds__(256, 2)
gemm128(const float* __restrict__ A, const float* __restrict__ G, size_t gStride,
        const float* __restrict__ addend, float* __restrict__ C) {
    const int b  = blockIdx.y;
    const int n0 = blockIdx.x * 64;
    const float* Ab = A + (size_t)b*(2*CC)*NN;
    const float* Gb = G + (size_t)b*gStride;
    __shared__ float As[2][16*PADA];
    __shared__ float Gs[2][16*PADG];
    const int tid = threadIdx.x;
    const int tx = tid & 15, ty = tid >> 4;

    const int ac = tid >> 1;
    const int ak = (tid & 1) * 8;
    const float* Aptr = Ab + (size_t)ac*NN + ak;
    const int gr = tid >> 4;
    const int gm = (tid & 15) * 4;
    const float* Gptr = Gb + (size_t)gr*NN + n0 + gm;

    float4 ra0 = *(const float4*)(Aptr);
    float4 ra1 = *(const float4*)(Aptr + 4);
    float4 rg  = *(const float4*)(Gptr);
    {
        float* as = &As[0][ak*PADA + ac];
        as[0*PADA]=ra0.x; as[1*PADA]=ra0.y; as[2*PADA]=ra0.z; as[3*PADA]=ra0.w;
        as[4*PADA]=ra1.x; as[5*PADA]=ra1.y; as[6*PADA]=ra1.z; as[7*PADA]=ra1.w;
        *(float4*)&Gs[0][gr*PADG + gm] = rg;
    }
    __syncthreads();

    u64 acc[4][4] = {};
    for (int t = 0; t < 64; ++t) {
        int cur = t & 1;
        if (t < 63) {
            const float* ap = Aptr + (t+1)*16;
            ra0 = *(const float4*)(ap);
            ra1 = *(const float4*)(ap + 4);
            rg  = *(const float4*)(Gptr + (size_t)(t+1)*16*NN);
        }
#pragma unroll
        for (int kk = 0; kk < 16; kk++) {
            const float* arow = &As[cur][kk*PADA + ty*8];
            ulonglong2 av0 = *(const ulonglong2*)(arow);
            ulonglong2 av1 = *(const ulonglong2*)(arow + 4);
            float4 g = *(const float4*)&Gs[cur][kk*PADG + tx*4];
            u64 gs0 = splat2(g.x), gs1 = splat2(g.y), gs2 = splat2(g.z), gs3 = splat2(g.w);
            ffma2(acc[0][0], av0.x, gs0); ffma2(acc[0][1], av0.x, gs1);
            ffma2(acc[0][2], av0.x, gs2); ffma2(acc[0][3], av0.x, gs3);
            ffma2(acc[1][0], av0.y, gs0); ffma2(acc[1][1], av0.y, gs1);
            ffma2(acc[1][2], av0.y, gs2); ffma2(acc[1][3], av0.y, gs3);
            ffma2(acc[2][0], av1.x, gs0); ffma2(acc[2][1], av1.x, gs1);
            ffma2(acc[2][2], av1.x, gs2); ffma2(acc[2][3], av1.x, gs3);
            ffma2(acc[3][0], av1.y, gs0); ffma2(acc[3][1], av1.y, gs1);
            ffma2(acc[3][2], av1.y, gs2); ffma2(acc[3][3], av1.y, gs3);
        }
        if (t < 63) {
            int nxt = cur ^ 1;
            float* as = &As[nxt][ak*PADA + ac];
            as[0*PADA]=ra0.x; as[1*PADA]=ra0.y; as[2*PADA]=ra0.z; as[3*PADA]=ra0.w;
            as[4*PADA]=ra1.x; as[5*PADA]=ra1.y; as[6*PADA]=ra1.z; as[7*PADA]=ra1.w;
            *(float4*)&Gs[nxt][gr*PADG + gm] = rg;
        }
        __syncthreads();
    }

    float* Cb = C + (size_t)b*(2*CC)*NN + n0;
    const float* Db = addend ? addend + (size_t)b*(2*CC)*NN + n0 : nullptr;
#pragma unroll
    for (int i = 0; i < 4; i++) {
        int m = ty*8 + 2*i;
        float2 v0 = unpack2(acc[i][0]), v1 = unpack2(acc[i][1]);
        float2 v2 = unpack2(acc[i][2]), v3 = unpack2(acc[i][3]);
        float4 lo = {v0.x, v1.x, v2.x, v3.x};
        float4 hi = {v0.y, v1.y, v2.y, v3.y};
        if (Db) {
            float4 d0 = *(const float4*)(Db + (size_t)m*NN + tx*4);
            float4 d1 = *(const float4*)(Db + (size_t)(m+1)*NN + tx*4);
            lo.x += d0.x; lo.y += d0.y; lo.z += d0.z; lo.w += d0.w;
            hi.x += d1.x; hi.y += d1.y; hi.z += d1.z; hi.w += d1.w;
        }
        *(float4*)(Cb + (size_t)m*NN + tx*4) = lo;
        *(float4*)(Cb + (size_t)(m+1)*NN + tx*4) = hi;
    }
}

// ================= gemm64T: C[b,c,m] = sum_k A[b,c,k] * G[m,k]  (G row-major [m][k]) ===
// 64 channels. Optional bias[m] (N axis) and relu.
template<int RELU>
__global__ void __launch_bounds__(128)
gemm64T(const float* __restrict__ A, const float* __restrict__ G, size_t gStride,
        const float* __restrict__ bias, float* __restrict__ C) {
    const int b  = blockIdx.y;
    const int n0 = blockIdx.x * 64;
    const float* Ab = A + (size_t)b*CC*NN;
    const float* Gb = G + (size_t)b*gStride;
    __shared__ float As[2][16*PADG];
    __shared__ float Gs[2][16*PADG];
    const int tid = threadIdx.x;
    const int tx = tid & 15, ty = tid >> 4;   // ty 0..7

    const int ac = tid >> 1;
    const int ak = (tid & 1) * 8;
    const float* Aptr = Ab + (size_t)ac*NN + ak;
    const int gmr = tid >> 1;
    const int gk  = (tid & 1) * 8;
    const float* Gptr = Gb + (size_t)(n0 + gmr)*NN + gk;

    float4 ra0 = *(const float4*)(Aptr);
    float4 ra1 = *(const float4*)(Aptr + 4);
    float4 rg0 = *(const float4*)(Gptr);
    float4 rg1 = *(const float4*)(Gptr + 4);
    {
        float* as = &As[0][ak*PADG + ac];
        as[0*PADG]=ra0.x; as[1*PADG]=ra0.y; as[2*PADG]=ra0.z; as[3*PADG]=ra0.w;
        as[4*PADG]=ra1.x; as[5*PADG]=ra1.y; as[6*PADG]=ra1.z; as[7*PADG]=ra1.w;
        float* gsp = &Gs[0][gk*PADG + gmr];
        gsp[0*PADG]=rg0.x; gsp[1*PADG]=rg0.y; gsp[2*PADG]=rg0.z; gsp[3*PADG]=rg0.w;
        gsp[4*PADG]=rg1.x; gsp[5*PADG]=rg1.y; gsp[6*PADG]=rg1.z; gsp[7*PADG]=rg1.w;
    }
    __syncthreads();

    u64 acc[4][4] = {};
    for (int t = 0; t < 64; ++t) {
        int cur = t & 1;
        if (t < 63) {
            const float* ap = Aptr + (t+1)*16;
            ra0 = *(const float4*)(ap);
            ra1 = *(const float4*)(ap + 4);
            const float* gp = Gptr + (t+1)*16;
            rg0 = *(const float4*)(gp);
            rg1 = *(const float4*)(gp + 4);
        }
#pragma unroll
        for (int kk = 0; kk < 16; kk++) {
            const float* arow = &As[cur][kk*PADG + ty*8];
            ulonglong2 av0 = *(const ulonglong2*)(arow);
            ulonglong2 av1 = *(const ulonglong2*)(arow + 4);
            float4 g = *(const float4*)&Gs[cur][kk*PADG + tx*4];
            u64 gs0 = splat2(g.x), gs1 = splat2(g.y), gs2 = splat2(g.z), gs3 = splat2(g.w);
            ffma2(acc[0][0], av0.x, gs0); ffma2(acc[0][1], av0.x, gs1);
            ffma2(acc[0][2], av0.x, gs2); ffma2(acc[0][3], av0.x, gs3);
            ffma2(acc[1][0], av0.y, gs0); ffma2(acc[1][1], av0.y, gs1);
            ffma2(acc[1][2], av0.y, gs2); ffma2(acc[1][3], av0.y, gs3);
            ffma2(acc[2][0], av1.x, gs0); ffma2(acc[2][1], av1.x, gs1);
            ffma2(acc[2][2], av1.x, gs2); ffma2(acc[2][3], av1.x, gs3);
            ffma2(acc[3][0], av1.y, gs0); ffma2(acc[3][1], av1.y, gs1);
            ffma2(acc[3][2], av1.y, gs2); ffma2(acc[3][3], av1.y, gs3);
        }
        if (t < 63) {
            int nxt = cur ^ 1;
            float* as = &As[nxt][ak*PADG + ac];
            as[0*PADG]=ra0.x; as[1*PADG]=ra0.y; as[2*PADG]=ra0.z; as[3*PADG]=ra0.w;
            as[4*PADG]=ra1.x; as[5*PADG]=ra1.y; as[6*PADG]=ra1.z; as[7*PADG]=ra1.w;
            float* gsp = &Gs[nxt][gk*PADG + gmr];
            gsp[0*PADG]=rg0.x; gsp[1*PADG]=rg0.y; gsp[2*PADG]=rg0.z; gsp[3*PADG]=rg0.w;
            gsp[4*PADG]=rg1.x; gsp[5*PADG]=rg1.y; gsp[6*PADG]=rg1.z; gsp[7*PADG]=rg1.w;
        }
        __syncthreads();
    }

    float4 bv = {0.f,0.f,0.f,0.f};
    if (bias) bv = *(const float4*)(bias + n0 + tx*4);
    float* Cb = C + (size_t)b*CC*NN + n0;
#pragma unroll
    for (int i = 0; i < 4; i++) {
        int m = ty*8 + 2*i;
        float2 v0 = unpack2(acc[i][0]), v1 = unpack2(acc[i][1]);
        float2 v2 = unpack2(acc[i][2]), v3 = unpack2(acc[i][3]);
        float4 lo = {v0.x + bv.x, v1.x + bv.y, v2.x + bv.z, v3.x + bv.w};
        float4 hi = {v0.y + bv.x, v1.y + bv.y, v2.y + bv.z, v3.y + bv.w};
        if (RELU) {
            lo.x = fmaxf(lo.x, 0.f); lo.y = fmaxf(lo.y, 0.f);
            lo.z = fmaxf(lo.z, 0.f); lo.w = fmaxf(lo.w, 0.f);
            hi.x = fmaxf(hi.x, 0.f); hi.y = fmaxf(hi.y, 0.f);
            hi.z = fmaxf(hi.z, 0.f); hi.w = fmaxf(hi.w, 0.f);
        }
        *(float4*)(Cb + (size_t)m*NN + tx*4) = lo;
        *(float4*)(Cb + (size_t)(m+1)*NN + tx*4) = hi;
    }
}

// ---------------- 64x64 channel mix (strided in/out) ----------------
template<int MTRANS>
__global__ void chanmix(const float* __restrict__ in, size_t inB, size_t inOff,
                        const float* __restrict__ M, const float* __restrict__ bias,
                        float* __restrict__ out, size_t outB, size_t outOff) {
    __shared__ float Ms[64][65];
    __shared__ float Xs[64][65];
    int tid = threadIdx.x;
    int b = blockIdx.y, n0 = blockIdx.x * 64;
    for (int i = tid; i < 64*64; i += 256) {
        int r = i >> 6, c = i & 63;
        Ms[r][c] = MTRANS ? M[c*64 + r] : M[i];
    }
    const float* inb = in + (size_t)b*inB + inOff + n0;
    for (int i = tid; i < 64*64; i += 256) {
        int k = i >> 6, n = i & 63;
        Xs[k][n] = inb[(size_t)k*NN + n];
    }
    __syncthreads();
    int tx = tid & 15, ty = tid >> 4;
    float acc[4][4] = {};
#pragma unroll 8
    for (int k = 0; k < 64; k++) {
        float m[4], xv[4];
#pragma unroll
        for (int i = 0; i < 4; i++) m[i] = Ms[ty + 16*i][k];
#pragma unroll
        for (int j = 0; j < 4; j++) xv[j] = Xs[k][tx + 16*j];
#pragma unroll
        for (int i = 0; i < 4; i++)
#pragma unroll
            for (int j = 0; j < 4; j++) acc[i][j] = fmaf(m[i], xv[j], acc[i][j]);
    }
    float* outb = out + (size_t)b*outB + outOff + n0;
#pragma unroll
    for (int i = 0; i < 4; i++) {
        int o = ty + 16*i;
        float bv = bias ? bias[o] : 0.f;
#pragma unroll
        for (int j = 0; j < 4; j++)
            outb[(size_t)o*NN + tx + 16*j] = acc[i][j] + bv;
    }
}

// ---------------- attention scores (rank-1) ----------------
__global__ void k_s12(const float* __restrict__ att_a) {
    __shared__ float a1[64], a2[64];
    int t = threadIdx.x;
    if (t < 64) a1[t] = att_a[t];
    else if (t < 128) a2[t-64] = att_a[t];
    __syncthreads();
    int b = blockIdx.x;
    int i = blockIdx.y * 256 + t;
    const float* h = g_hT + (size_t)b*CC*NN + i;
    float v1 = 0.f, v2 = 0.f;
#pragma unroll 8
    for (int c = 0; c < 64; c++) {
        float hv = h[(size_t)c*NN];
        v1 = fmaf(hv, a1[c], v1);
        v2 = fmaf(hv, a2[c], v2);
    }
    g_s1[b*NN + i] = v1;
    g_s2[b*NN + i] = v2;
}

__global__ void k_attrow() {
    int b = blockIdx.y, i = blockIdx.x, t = threadIdx.x;
    float s1 = g_s1[b*NN + i];
    const float* s2 = g_s2 + b*NN;
    float v[4];
    float mx = -1e30f;
#pragma unroll
    for (int q = 0; q < 4; q++) {
        float e = s1 + s2[t + 256*q];
        e = (e > 0.f) ? e : 0.01f*e;
        v[q] = e;
        mx = fmaxf(mx, e);
    }
    __shared__ float sh[256];
    sh[t] = mx; __syncthreads();
    for (int o = 128; o > 0; o >>= 1) { if (t < o) sh[t] = fmaxf(sh[t], sh[t+o]); __syncthreads(); }
    mx = sh[0]; __syncthreads();
    float sm = 0.f;
#pragma unroll
    for (int q = 0; q < 4; q++) { v[q] = __expf(v[q] - mx); sm += v[q]; }
    sh[t] = sm; __syncthreads();
    for (int o = 128; o > 0; o >>= 1) { if (t < o) sh[t] += sh[t+o]; __syncthreads(); }
    float inv = 1.f / sh[0];
    float* arow = g_att + ((size_t)b*NN + i)*NN;
#pragma unroll
    for (int q = 0; q < 4; q++) arow[t + 256*q] = v[q] * inv;
}

// ---------------- learned adjacency (gram + rbf) ----------------
__global__ void k_sq() {
    int b = blockIdx.x, n = blockIdx.y * 256 + threadIdx.x;
    const float* xp = g_xuai + (size_t)b*CC*NN + n;
    float s = 0.f;
#pragma unroll 8
    for (int c = 0; c < CC; c++) { float v = xp[(size_t)c*NN]; s = fmaf(v, v, s); }
    g_sq[b*NN + n] = s;
}

__global__ void k_gram() {
    int b = blockIdx.z;
    int i0 = blockIdx.x * 64, j0 = blockIdx.y * 64;
    __shared__ float Xi[64][65], Xj[64][65];
    const float* X = g_xuai + (size_t)b*CC*NN;
    int tid = threadIdx.x;
    for (int p = tid; p < 64*64; p += 256) {
        int c = p >> 6, q = p & 63;
        Xi[c][q] = X[(size_t)c*NN + i0 + q];
        Xj[c][q] = X[(size_t)c*NN + j0 + q];
    }
    __syncthreads();
    int tx = tid & 15, ty = tid >> 4;
    float acc[4][4] = {};
#pragma unroll 8
    for (int c = 0; c < 64; c++) {
        float a[4], g[4];
#pragma unroll
        for (int p = 0; p < 4; p++) a[p] = Xi[c][ty + 16*p];
#pragma unroll
        for (int q = 0; q < 4; q++) g[q] = Xj[c][tx + 16*q];
#pragma unroll
        for (int p = 0; p < 4; p++)
#pragma unroll
            for (int q = 0; q < 4; q++) acc[p][q] = fmaf(a[p], g[q], acc[p][q]);
    }
    const float* sq = g_sq + b*NN;
    float* glb = g_gl + (size_t)b*NN*NN;
#pragma unroll
    for (int p = 0; p < 4; p++) {
        int i = i0 + ty + 16*p;
        float sqi = sq[i];
#pragma unroll
        for (int q = 0; q < 4; q++) {
            int j = j0 + tx + 16*q;
            float d2 = fmaxf(sqi + sq[j] - 2.f*acc[p][q], 0.f);
            float m = __expf(-d2 * (1.f/128.f)) + ((i == j) ? 1.f : 0.f);
            glb[(size_t)i*NN + j] = __expf(m);
        }
    }
}

__global__ void k_rownorm() {
    int b = blockIdx.y, i = blockIdx.x, t = threadIdx.x;
    float* row = g_gl + ((size_t)b*NN + i)*NN;
    float v[4]; float s = 0.f;
#pragma unroll
    for (int q = 0; q < 4; q++) { v[q] = row[t + 256*q]; s += v[q]; }
    __shared__ float sh[256];
    sh[t] = s; __syncthreads();
    for (int o = 128; o > 0; o >>= 1) { if (t < o) sh[t] += sh[t+o]; __syncthreads(); }
    float inv = 1.f / sh[0];
#pragma unroll
    for (int q = 0; q < 4; q++) row[t + 256*q] = v[q] * inv;
}

// ---------------- layernorm stats + final fuse ----------------
__global__ void k_lnstats() {
    int b = blockIdx.x, path = blockIdx.y, t = threadIdx.x;
    const float* z = g_s12x + (size_t)b*(2*CC)*NN + (size_t)path*CC*NN;
    float s = 0.f, ss = 0.f;
    for (int i = t; i < CC*NN; i += 1024) { float v = z[i]; s += v; ss = fmaf(v, v, ss); }
    __shared__ float shs[1024], shq[1024];
    shs[t] = s; shq[t] = ss; __syncthreads();
    for (int o = 512; o > 0; o >>= 1) {
        if (t < o) { shs[t] += shs[t+o]; shq[t] += shq[t+o]; }
        __syncthreads();
    }
    if (t == 0) {
        float mean = shs[0] * (1.f/65536.f);
        float var  = shq[0] * (1.f/65536.f) - mean*mean;
        g_stats[(path*BB + b)*2 + 0] = mean;
        g_stats[(path*BB + b)*2 + 1] = rsqrtf(var + 1e-5f);
    }
}

__global__ void k_final(const float* __restrict__ ct, const float* __restrict__ ln_w,
                        const float* __restrict__ ln_b, float* __restrict__ out) {
    size_t idx = (size_t)blockIdx.x * 256 + threadIdx.x;
    int b  = (int)(idx / (CC*NN));
    int cn = (int)(idx % (CC*NN));
    float m1 = g_stats[b*2 + 0],            r1 = g_stats[b*2 + 1];
    float m2 = g_stats[(BB + b)*2 + 0],     r2 = g_stats[(BB + b)*2 + 1];
    float w = ln_w[cn], bb = ln_b[cn];
    size_t base = (size_t)b*(2*CC)*NN + cn;
    float xnew = (g_s12x[base]             - m1) * r1 * w + bb;
    float z2   = (g_s12x[base + (size_t)CC*NN] - m2) * r2 * w + bb;
    float ft = 0.5f * z2 * (1.f + erff(z2 * 0.70710678118654752f));
    float ctv = ct[idx];
    float ctn = xnew + ft * (ctv - xnew);
    float el  = (ctn > 0.f) ? ctn : expm1f(ctn);
    float xu  = g_xuai[idx];
    float ht  = xu + ft * (el - xu);
    out[idx] = ht;
    out[(size_t)BB*CC*NN + idx] = ctn;
}

// ---------------- host launch ----------------
struct DevPtrs {
    float *att, *gl, *g1, *g2, *h0a, *h0, *hT, *xatt, *xuai;
    float *l12, *t12, *u12, *a12, *s12x;
    bool init;
};
static DevPtrs P = {};

static void init_ptrs() {
    if (P.init) return;
    void* p;
#define GET(sym, field) cudaGetSymbolAddress(&p, sym); P.field = (float*)p;
    GET(g_att, att)  GET(g_gl, gl)   GET(g_g1, g1)   GET(g_g2, g2)
    GET(g_h0a, h0a)  GET(g_h0, h0)   GET(g_hT, hT)   GET(g_xatt, xatt)
    GET(g_xuai, xuai) GET(g_l12, l12) GET(g_t12, t12) GET(g_u12, u12)
    GET(g_a12, a12)  GET(g_s12x, s12x)
#undef GET
    P.init = true;
}

extern "C" void kernel_launch(void* const* d_in, const int* in_sizes, int n_in,
                              void* d_out, int out_size) {
    const float* x      = (const float*)d_in[0];
    const float* ct     = (const float*)d_in[1];
    const float* graph  = (const float*)d_in[2];
    const float* emb_w  = (const float*)d_in[3];
    const float* emb_b  = (const float*)d_in[4];
    const float* emb2_w = (const float*)d_in[5];
    const float* emb2_b = (const float*)d_in[6];
    const float* att_W  = (const float*)d_in[7];
    const float* att_a  = (const float*)d_in[8];
    // d_in[9] = att_GL : unused (softmax output strictly positive => mask no-op)
    const float* uai_w  = (const float*)d_in[10];
    const float* uai_b  = (const float*)d_in[11];
    const float* lin1_w = (const float*)d_in[12];
    const float* lin2_w = (const float*)d_in[13];
    const float* lin2_b = (const float*)d_in[14];
    const float* ln_w   = (const float*)d_in[15];
    const float* ln_b   = (const float*)d_in[16];
    float* out = (float*)d_out;

    init_ptrs();

    const dim3 grid64(NN/64, BB);
    const size_t GSTRIDE = (size_t)NN * NN;
    const size_t SB = (size_t)CC*NN;        // 64-ch batch stride
    const size_t DB = (size_t)2*CC*NN;      // 128-ch batch stride

    // graph laplacians
    k_lap_d    <<<dim3(NN, 2), 256>>>(graph);
    k_lap_scale<<<dim3(32, 32, 2), dim3(32, 8)>>>(graph);

    // embedding
    k_emb1<<<dim3(BB, NN/256), 256>>>(x, emb_w, emb_b);
    gemm64T<0><<<grid64, 128>>>(P.h0a, emb2_w, 0, emb2_b, P.h0);

    // attention
    chanmix<1><<<grid64, 256>>>(P.h0, SB, 0, att_W, nullptr, P.hT, SB, 0);
    k_s12   <<<dim3(BB, NN/256), 256>>>(att_a);
    k_attrow<<<dim3(NN, BB), 256>>>();
    gemm64T<1><<<grid64, 128>>>(P.hT, P.att, GSTRIDE, nullptr, P.xatt);

    // UAI linear
    chanmix<0><<<grid64, 256>>>(P.xatt, SB, 0, uai_w, uai_b, P.xuai, SB, 0);

    // learned adjacency gl
    k_sq     <<<dim3(BB, NN/256), 256>>>();
    k_gram   <<<dim3(16, 16, BB), 256>>>();
    k_rownorm<<<dim3(NN, BB), 256>>>();

    // l1/l2 stacked propagation
    chanmix<0><<<grid64, 256>>>(P.xuai, SB, 0, lin1_w, nullptr, P.l12, DB, 0);
    chanmix<0><<<grid64, 256>>>(P.xuai, SB, 0, lin2_w, lin2_b, P.l12, DB, SB);

    gemm128<<<grid64, 256>>>(P.l12, P.gl, GSTRIDE, nullptr, P.a12);
    gemm128<<<grid64, 256>>>(P.l12, P.g1, 0, nullptr, P.t12);

    chanmix<0><<<grid64, 256>>>(P.t12, DB, 0,  lin1_w, nullptr, P.u12, DB, 0);
    chanmix<0><<<grid64, 256>>>(P.t12, DB, SB, lin2_w, lin2_b, P.u12, DB, SB);

    gemm128<<<grid64, 256>>>(P.u12, P.g2, 0, P.a12, P.s12x);

    // layernorm + gates + output
    k_lnstats<<<dim3(BB, 2), 1024>>>();
    k_final  <<<(BB*CC*NN)/256, 256>>>(ct, ln_w, ln_b, out);
}